// round 4
// baseline (speedup 1.0000x reference)
#include <cuda_runtime.h>
#include <stdint.h>
#include <math.h>

#define HEADS 16
#define DH    64
#define BATCH 8
#define SEQ   512
#define DMODEL 1024
#define INNER 1024            // HEADS*DH
#define QKV_N 3072            // 3*INNER
#define NTOK  4096            // BATCH*SEQ

// Scratch (device globals: allocation-free, graph-capture safe)
__device__ float g_qkv[(size_t)NTOK * QKV_N];               // 48 MB
__device__ float g_dots[(size_t)BATCH * HEADS * SEQ * SEQ]; // 128 MB
__device__ float g_av[(size_t)NTOK * INNER];                // 16 MB

// ---------------------------------------------------------------------------
__device__ __forceinline__ uint32_t f2tf32(float x) {
    uint32_t u;
    asm("cvt.rna.tf32.f32 %0, %1;" : "=r"(u) : "f"(x));
    return u;
}

__device__ __forceinline__ void mma8(float* c, const uint32_t* a, const uint32_t* b) {
    asm volatile(
        "mma.sync.aligned.m16n8k8.row.col.f32.tf32.tf32.f32 "
        "{%0,%1,%2,%3}, {%4,%5,%6,%7}, {%8,%9}, {%0,%1,%2,%3};"
        : "+f"(c[0]), "+f"(c[1]), "+f"(c[2]), "+f"(c[3])
        : "r"(a[0]), "r"(a[1]), "r"(a[2]), "r"(a[3]),
          "r"(b[0]), "r"(b[1]));
}

// ---------------------------------------------------------------------------
// Unified tf32 tensor-core GEMM: register-staged prefetch + DOUBLE-BUFFERED
// smem (one __syncthreads per K-tile; STS targets the inactive buffer).
// MODE 0: QKV proj   MODE 1: OUT proj (+bias)
// MODE 2: AV (per bh)  MODE 3: DOTS (per bh, alpha=0.125, B n-major)
// 256 threads (8 warps 4x2), BM x BN tile, BK=32.
// ---------------------------------------------------------------------------
template<int MODE, int BM, int BN, int KTOT>
__global__ void __launch_bounds__(256) mma_gemm(
    const float* __restrict__ gA, const float* __restrict__ gB,
    const float* __restrict__ bias, float* __restrict__ gC)
{
    constexpr int MI = BM / 64;
    constexpr int NI = BN / 16;
    constexpr int LDB_S = BN + 4;
    constexpr int ASZ = BM * 36;
    constexpr int BSZ = (MODE == 3) ? BN * 36 : 32 * LDB_S;
    constexpr int NLDA = BM / 32;
    constexpr int NLDB = BN / 32;

    __shared__ uint32_t sA[2][ASZ];
    __shared__ uint32_t sB[2][BSZ];

    const int tid  = threadIdx.x;
    const int row0 = blockIdx.y * BM;
    const int col0 = blockIdx.x * BN;

    const float* A;
    const float* B;
    float* C;
    size_t lda, ldb, ldc;
    float alpha = 1.0f;

    if (MODE == 0) {
        A = gA; lda = DMODEL; B = gB; ldb = QKV_N; C = gC; ldc = QKV_N;
    } else if (MODE == 1) {
        A = gA; lda = DMODEL; B = gB; ldb = DMODEL; C = gC; ldc = DMODEL;
    } else if (MODE == 2) {
        const int bh = blockIdx.z, b = bh >> 4, h = bh & 15;
        A = gA + (size_t)bh * SEQ * SEQ;                               lda = SEQ;
        B = gB + (size_t)b * SEQ * QKV_N + 2 * INNER + (size_t)h * DH; ldb = QKV_N;
        C = gC + (size_t)b * SEQ * INNER + (size_t)h * DH;             ldc = INNER;
    } else {
        const int bh = blockIdx.z, b = bh >> 4, h = bh & 15;
        A = gA + (size_t)b * SEQ * QKV_N + (size_t)h * DH;             lda = QKV_N;
        B = gB + (size_t)b * SEQ * QKV_N + INNER + (size_t)h * DH;     ldb = QKV_N;
        C = gC + (size_t)bh * SEQ * SEQ;                               ldc = SEQ;
        alpha = 0.125f;
    }

    const int warp = tid >> 5, lane = tid & 31;
    const int wm = warp >> 1, wn = warp & 1;
    const int g = lane >> 2, t4 = lane & 3;

    const int aR  = tid >> 3;           // A/mode3-B row base
    const int aC4 = tid & 7;
    const int bRk = tid / (BN / 4);     // k-major B row
    const int bCk = tid % (BN / 4);

    float4 ra[NLDA], rb[NLDB];

    auto loadA = [&](int k0) {
        #pragma unroll
        for (int t = 0; t < NLDA; t++) {
            int r = aR + t * 32;
            ra[t] = *reinterpret_cast<const float4*>(
                &A[(size_t)(row0 + r) * lda + k0 + aC4 * 4]);
        }
    };
    auto stsA = [&](uint32_t* dst) {
        #pragma unroll
        for (int t = 0; t < NLDA; t++) {
            int r = aR + t * 32;
            uint4 u;
            u.x = f2tf32(ra[t].x); u.y = f2tf32(ra[t].y);
            u.z = f2tf32(ra[t].z); u.w = f2tf32(ra[t].w);
            *reinterpret_cast<uint4*>(&dst[r * 36 + aC4 * 4]) = u;
        }
    };
    auto loadB = [&](int k0) {
        if (MODE == 3) {
            #pragma unroll
            for (int t = 0; t < NLDB; t++) {
                int r = aR + t * 32;
                rb[t] = *reinterpret_cast<const float4*>(
                    &B[(size_t)(col0 + r) * ldb + k0 + aC4 * 4]);
            }
        } else {
            #pragma unroll
            for (int t = 0; t < NLDB; t++) {
                int r = bRk + t * (1024 / BN);
                rb[t] = *reinterpret_cast<const float4*>(
                    &B[(size_t)(k0 + r) * ldb + col0 + bCk * 4]);
            }
        }
    };
    auto stsB = [&](uint32_t* dst) {
        if (MODE == 3) {
            #pragma unroll
            for (int t = 0; t < NLDB; t++) {
                int r = aR + t * 32;
                uint4 u;
                u.x = f2tf32(rb[t].x); u.y = f2tf32(rb[t].y);
                u.z = f2tf32(rb[t].z); u.w = f2tf32(rb[t].w);
                *reinterpret_cast<uint4*>(&dst[r * 36 + aC4 * 4]) = u;
            }
        } else {
            #pragma unroll
            for (int t = 0; t < NLDB; t++) {
                int r = bRk + t * (1024 / BN);
                uint4 u;
                u.x = f2tf32(rb[t].x); u.y = f2tf32(rb[t].y);
                u.z = f2tf32(rb[t].z); u.w = f2tf32(rb[t].w);
                *reinterpret_cast<uint4*>(&dst[r * LDB_S + bCk * 4]) = u;
            }
        }
    };

    float acc[MI][NI][4] = {};

    // Prologue: stage + commit tile 0 into buffer 0
    loadA(0); loadB(0);
    stsA(sA[0]); stsB(sB[0]);
    __syncthreads();

    int cur = 0;
    for (int k0 = 0; k0 < KTOT; k0 += 32) {
        const bool more = (k0 + 32 < KTOT);
        if (more) { loadA(k0 + 32); loadB(k0 + 32); }   // LDG overlaps MMA

        const uint32_t* cA = sA[cur];
        const uint32_t* cB = sB[cur];

        #pragma unroll
        for (int kk = 0; kk < 4; kk++) {
            const int k = kk * 8;
            uint32_t af[MI][4];
            #pragma unroll
            for (int mi = 0; mi < MI; mi++) {
                int r = wm * (BM / 4) + mi * 16 + g;
                af[mi][0] = cA[r * 36 + k + t4];
                af[mi][1] = cA[(r + 8) * 36 + k + t4];
                af[mi][2] = cA[r * 36 + k + 4 + t4];
                af[mi][3] = cA[(r + 8) * 36 + k + 4 + t4];
            }
            uint32_t bf[NI][2];
            #pragma unroll
            for (int ni = 0; ni < NI; ni++) {
                int c = wn * (BN / 2) + ni * 8 + g;
                if (MODE == 3) {
                    bf[ni][0] = cB[c * 36 + k + t4];
                    bf[ni][1] = cB[c * 36 + k + 4 + t4];
                } else {
                    bf[ni][0] = cB[(k + t4) * LDB_S + c];
                    bf[ni][1] = cB[(k + 4 + t4) * LDB_S + c];
                }
            }
            #pragma unroll
            for (int mi = 0; mi < MI; mi++)
                #pragma unroll
                for (int ni = 0; ni < NI; ni++)
                    mma8(acc[mi][ni], af[mi], bf[ni]);
        }

        if (more) {
            // Write NEXT tile into the inactive buffer — no pre-STS barrier
            // needed (nobody reads that buffer until after the sync below).
            stsA(sA[cur ^ 1]); stsB(sB[cur ^ 1]);
            __syncthreads();
            cur ^= 1;
        }
    }

    // Epilogue
    #pragma unroll
    for (int mi = 0; mi < MI; mi++) {
        int r = row0 + wm * (BM / 4) + mi * 16 + g;
        #pragma unroll
        for (int ni = 0; ni < NI; ni++) {
            int c = col0 + wn * (BN / 2) + ni * 8 + 2 * t4;
            float b0 = 0.f, b1 = 0.f;
            if (MODE == 1) { b0 = bias[c]; b1 = bias[c + 1]; }
            float2 v0, v1;
            v0.x = acc[mi][ni][0] * alpha + b0;
            v0.y = acc[mi][ni][1] * alpha + b1;
            v1.x = acc[mi][ni][2] * alpha + b0;
            v1.y = acc[mi][ni][3] * alpha + b1;
            *reinterpret_cast<float2*>(&C[(size_t)r * ldc + c]) = v0;
            *reinterpret_cast<float2*>(&C[(size_t)(r + 8) * ldc + c]) = v1;
        }
    }
}

// ---------------------------------------------------------------------------
// Fused: per (b,i) — softmax over j per head, 16x16 head mix, LayerNorm over
// heads, gamma/beta. In-place on g_dots.
// ---------------------------------------------------------------------------
__global__ void __launch_bounds__(256) softmax_mix_ln_kernel(
    float* __restrict__ dots, const float* __restrict__ W,
    const float* __restrict__ gamma, const float* __restrict__ beta)
{
    const int bi = blockIdx.x;
    const int b  = bi >> 9;
    const int i  = bi & 511;

    __shared__ float sc[HEADS][SEQ];
    __shared__ float wmat[HEADS][HEADS];
    __shared__ float sg[HEADS], sb[HEADS];

    const int tid = threadIdx.x;
    wmat[tid >> 4][tid & 15] = W[tid];
    if (tid < HEADS) { sg[tid] = gamma[tid]; sb[tid] = beta[tid]; }

    #pragma unroll
    for (int t = 0; t < 8; t++) {
        int idx = tid + t * 256;
        int h   = idx >> 7;
        int j4  = idx & 127;
        float4 v = *reinterpret_cast<const float4*>(
            &dots[((size_t)(b * HEADS + h) * SEQ + i) * SEQ + j4 * 4]);
        *reinterpret_cast<float4*>(&sc[h][j4 * 4]) = v;
    }
    __syncthreads();

    const int warp = tid >> 5, lane = tid & 31;
    #pragma unroll
    for (int hh = 0; hh < 2; hh++) {
        int h = warp * 2 + hh;
        float mx = -1e30f;
        for (int j = lane; j < SEQ; j += 32) mx = fmaxf(mx, sc[h][j]);
        #pragma unroll
        for (int o = 16; o > 0; o >>= 1)
            mx = fmaxf(mx, __shfl_xor_sync(0xffffffffu, mx, o));
        float s = 0.f;
        for (int j = lane; j < SEQ; j += 32) {
            float e = __expf(sc[h][j] - mx);
            sc[h][j] = e;
            s += e;
        }
        #pragma unroll
        for (int o = 16; o > 0; o >>= 1)
            s += __shfl_xor_sync(0xffffffffu, s, o);
        float inv = 1.f / s;
        for (int j = lane; j < SEQ; j += 32) sc[h][j] *= inv;
    }
    __syncthreads();

    for (int j = tid; j < SEQ; j += 256) {
        float a[HEADS];
        #pragma unroll
        for (int h = 0; h < HEADS; h++) a[h] = sc[h][j];
        float mixed[HEADS];
        #pragma unroll
        for (int gg = 0; gg < HEADS; gg++) {
            float s = 0.f;
            #pragma unroll
            for (int h = 0; h < HEADS; h++) s = fmaf(a[h], wmat[h][gg], s);
            mixed[gg] = s;
        }
        float mean = 0.f;
        #pragma unroll
        for (int gg = 0; gg < HEADS; gg++) mean += mixed[gg];
        mean *= (1.f / HEADS);
        float var = 0.f;
        #pragma unroll
        for (int gg = 0; gg < HEADS; gg++) {
            float d = mixed[gg] - mean;
            var = fmaf(d, d, var);
        }
        var *= (1.f / HEADS);
        float inv = rsqrtf(var + 1e-3f);
        #pragma unroll
        for (int gg = 0; gg < HEADS; gg++) {
            float y = (mixed[gg] - mean) * inv * sg[gg] + sb[gg];
            dots[((size_t)(b * HEADS + gg) * SEQ + i) * SEQ + j] = y;
        }
    }
}

// ---------------------------------------------------------------------------
extern "C" void kernel_launch(void* const* d_in, const int* in_sizes, int n_in,
                              void* d_out, int out_size)
{
    const float* x        = (const float*)d_in[0];
    const float* w_qkv    = (const float*)d_in[1];
    const float* reattn_w = (const float*)d_in[2];
    const float* ln_gamma = (const float*)d_in[3];
    const float* ln_beta  = (const float*)d_in[4];
    const float* w_out    = (const float*)d_in[5];
    const float* b_out    = (const float*)d_in[6];
    float* out = (float*)d_out;

    float *qkv = nullptr, *dots = nullptr, *av = nullptr;
    cudaGetSymbolAddress((void**)&qkv,  g_qkv);
    cudaGetSymbolAddress((void**)&dots, g_dots);
    cudaGetSymbolAddress((void**)&av,   g_av);

    dim3 blk(256);

    // 1) QKV projection
    mma_gemm<0, 128, 128, 1024><<<dim3(QKV_N / 128, NTOK / 128), blk>>>(
        x, w_qkv, nullptr, qkv);

    // 2) dots = 0.125 * Q K^T per (b,h)
    mma_gemm<3, 128, 128, 64><<<dim3(SEQ / 128, SEQ / 128, BATCH * HEADS), blk>>>(
        qkv, qkv, nullptr, dots);

    // 3) fused softmax + head mix + LayerNorm (in place)
    softmax_mix_ln_kernel<<<BATCH * SEQ, blk>>>(dots, reattn_w, ln_gamma, ln_beta);

    // 4) AV
    mma_gemm<2, 128, 64, 512><<<dim3(1, SEQ / 128, BATCH * HEADS), blk>>>(
        dots, qkv, nullptr, av);

    // 5) output projection + bias
    mma_gemm<1, 128, 128, 1024><<<dim3(DMODEL / 128, NTOK / 128), blk>>>(
        av, w_out, b_out, out);
}